// round 6
// baseline (speedup 1.0000x reference)
#include <cuda_runtime.h>

// out[t, 0, :] = inputs[t, :]
// out[t, l, :] = memory[l, :]  for l in [1, 64)
// T=2048, L=64, D=1024 (fp32). 512 MB pure-write kernel.
//
// Schedule (best = R3 base + 2-row blocks):
//   grid (x = l-pair fast, y = t-chunk), TT=16 t-rows per chunk (4 MB span).
//   Resident wave spans ~37 chunks * 4MB = 148MB = 74 pages < 128 TLB entries.
//   Each block owns TWO adjacent l-rows, register-held, emitting two
//   interleaved streaming-store streams (32 STG.128/thread) -> long per-block
//   streams + high store MLP, no steady-state loads.

constexpr int T  = 2048;
constexpr int L  = 64;
constexpr int D  = 1024;
constexpr int D4 = D / 4;            // 256 float4 per row -> 256 threads
constexpr int ROW4 = L * D4;         // float4 per t
constexpr int TT = 16;               // t-values per block chunk (4 MB)
constexpr int CH = T / TT;           // 128 chunks along t
constexpr int LP = 2;                // l-rows per block
constexpr int LB = L / LP;           // 32 l-blocks per chunk

__global__ __launch_bounds__(256, 8)
void sliding_window_memory_kernel(const float4* __restrict__ inp,
                                  const float4* __restrict__ mem,
                                  float4* __restrict__ out) {
    const int lb  = blockIdx.x;          // 0..31 (fast dim)
    const int l0  = lb * LP;             // first l of the pair
    const int t0  = blockIdx.y * TT;
    const int tid = threadIdx.x;         // float4 column 0..255

    if (lb == 0) {
        // l=0 (inputs[t]) + l=1 (register row)
        const float4 v1 = __ldg(mem + (size_t)1 * D4 + tid);
        const float4* ip = inp + (size_t)t0 * D4 + tid;
        float4*       op = out + (size_t)t0 * ROW4 + tid;
        #pragma unroll
        for (int i = 0; i < TT; ++i) {
            __stcs(op,      __ldcs(ip));   // slot 0
            __stcs(op + D4, v1);           // slot 1
            ip += D4;
            op += ROW4;
        }
    } else {
        // two t-invariant rows -> two register-held streaming stores
        const float4 v0 = __ldg(mem + (size_t)l0       * D4 + tid);
        const float4 v1 = __ldg(mem + (size_t)(l0 + 1) * D4 + tid);
        float4* op = out + (size_t)t0 * ROW4 + (size_t)l0 * D4 + tid;
        #pragma unroll
        for (int i = 0; i < TT; ++i) {
            __stcs(op,      v0);
            __stcs(op + D4, v1);
            op += ROW4;
        }
    }
}

extern "C" void kernel_launch(void* const* d_in, const int* in_sizes, int n_in,
                              void* d_out, int out_size) {
    const float4* inp = (const float4*)d_in[0];   // [T, D] fp32
    const float4* mem = (const float4*)d_in[1];   // [L, D] fp32
    float4* out = (float4*)d_out;                 // [T, L, D] fp32

    dim3 grid(LB, CH);
    sliding_window_memory_kernel<<<grid, 256>>>(inp, mem, out);
}